// round 8
// baseline (speedup 1.0000x reference)
#include <cuda_runtime.h>
#include <cuda_bf16.h>
#include <stdint.h>

// Problem constants (from reference)
#define ENTITIES_N 100000
#define RELATIONS_N 1000
#define BATCH 1024
#define WIDTH (2 * ENTITIES_N + RELATIONS_N)   // 201000 floats/row
#define ROW_VEC (WIDTH / 4)                    // 50250 float4s/row (exact)

#define TPB 256

// Streaming 128-bit store (evict-first: output is write-once, never re-read).
__device__ __forceinline__ void stcs4(float4* p, float4 v) {
    asm volatile("st.global.cs.v4.f32 [%0], {%1, %2, %3, %4};"
                 :: "l"(p), "f"(v.x), "f"(v.y), "f"(v.z), "f"(v.w) : "memory");
}

// One block per row; all BATCH=1024 blocks are co-resident (single wave on
// 148 SMs x 8 blocks). Each block streams its full 804KB row.
__global__ void __launch_bounds__(TPB)
fused_onehot_row_kernel(const int* __restrict__ hID,
                        const int* __restrict__ rID,
                        const int* __restrict__ tID,
                        float* __restrict__ out) {
    const int row = blockIdx.x;
    const int c0 = __ldg(&hID[row]);
    const int c1 = ENTITIES_N + __ldg(&rID[row]);
    const int c2 = ENTITIES_N + RELATIONS_N + __ldg(&tID[row]);

    float4* row_out = (float4*)(out + (long long)row * WIDTH);
    const float4 z = make_float4(0.f, 0.f, 0.f, 0.f);

    // 50250 = 256*196 + 74. Main loop: 49 unrolled-by-4 strided iterations,
    // then a predicated tail.
    int j = threadIdx.x;
    #pragma unroll 4
    for (int it = 0; it < 196; ++it, j += TPB) {
        const int base = j * 4;
        float4 v = z;
        int d;
        d = c0 - base; if ((unsigned)d < 4u) ((float*)&v)[d] = 1.0f;
        d = c1 - base; if ((unsigned)d < 4u) ((float*)&v)[d] = 1.0f;
        d = c2 - base; if ((unsigned)d < 4u) ((float*)&v)[d] = 1.0f;
        stcs4(&row_out[j], v);
    }
    // Tail: j in [50176, 50250)
    if (j < ROW_VEC) {
        const int base = j * 4;
        float4 v = z;
        int d;
        d = c0 - base; if ((unsigned)d < 4u) ((float*)&v)[d] = 1.0f;
        d = c1 - base; if ((unsigned)d < 4u) ((float*)&v)[d] = 1.0f;
        d = c2 - base; if ((unsigned)d < 4u) ((float*)&v)[d] = 1.0f;
        stcs4(&row_out[j], v);
    }
}

extern "C" void kernel_launch(void* const* d_in, const int* in_sizes, int n_in,
                              void* d_out, int out_size) {
    // Inputs per metadata order: z (f32, unused), hID (i32), rID (i32), tID (i32)
    const int* hID = (const int*)d_in[1];
    const int* rID = (const int*)d_in[2];
    const int* tID = (const int*)d_in[3];
    float* out = (float*)d_out;

    fused_onehot_row_kernel<<<BATCH, TPB>>>(hID, rID, tID, out);
}

// round 13
// speedup vs baseline: 1.0082x; 1.0082x over previous
#include <cuda_runtime.h>
#include <cuda_bf16.h>
#include <stdint.h>

// Problem constants (from reference)
#define ENTITIES_N 100000
#define RELATIONS_N 1000
#define BATCH 1024
#define WIDTH (2 * ENTITIES_N + RELATIONS_N)   // 201000 floats/row
#define ROW_VEC (WIDTH / 4)                    // 50250 float4s/row (exact)

#define TPB 256
#define VPT 8
#define CHUNK (TPB * VPT)                      // 2048 float4s per chunk
#define CHUNKS_PER_ROW ((ROW_VEC + CHUNK - 1) / CHUNK)   // 25
#define TOTAL_CHUNKS (CHUNKS_PER_ROW * BATCH)            // 25600

// Persistent grid: exactly fill residency (4 blocks/SM x 152 SMs on GB300).
#define GRID_BLOCKS (4 * 152)                  // 608

// Streaming 128-bit store (evict-first: output is write-once, never re-read).
__device__ __forceinline__ void stcs4(float4* p, float4 v) {
    asm volatile("st.global.cs.v4.f32 [%0], {%1, %2, %3, %4};"
                 :: "l"(p), "f"(v.x), "f"(v.y), "f"(v.z), "f"(v.w) : "memory");
}

__global__ void __launch_bounds__(TPB)
fused_onehot_persistent(const int* __restrict__ hID,
                        const int* __restrict__ rID,
                        const int* __restrict__ tID,
                        float* __restrict__ out) {
    const float4 z = make_float4(0.f, 0.f, 0.f, 0.f);

    for (int c = blockIdx.x; c < TOTAL_CHUNKS; c += GRID_BLOCKS) {
        const int row = c / CHUNKS_PER_ROW;            // const-div by 25 -> mul
        const int cir = c - row * CHUNKS_PER_ROW;

        // Three one-columns for this row (L1-broadcast, amortized over 32KB).
        const int c0 = __ldg(&hID[row]);
        const int c1 = ENTITIES_N + __ldg(&rID[row]);
        const int c2 = ENTITIES_N + RELATIONS_N + __ldg(&tID[row]);

        float4* row_out = (float4*)(out + (long long)row * WIDTH);
        const int chunk_lo = cir * CHUNK;              // first float4 idx
        const int col_lo   = chunk_lo * 4;

        const bool has_one =
            ((unsigned)(c0 - col_lo) < (unsigned)(CHUNK * 4)) |
            ((unsigned)(c1 - col_lo) < (unsigned)(CHUNK * 4)) |
            ((unsigned)(c2 - col_lo) < (unsigned)(CHUNK * 4));

        int j = chunk_lo + threadIdx.x;

        if (!has_one) {
            if (chunk_lo + CHUNK <= ROW_VEC) {
                // Hot path (~99.97% of chunks): pure streaming zero-fill.
                #pragma unroll
                for (int it = 0; it < VPT; ++it, j += TPB)
                    stcs4(&row_out[j], z);
            } else {
                #pragma unroll
                for (int it = 0; it < VPT; ++it, j += TPB)
                    if (j < ROW_VEC) stcs4(&row_out[j], z);
            }
        } else {
            #pragma unroll
            for (int it = 0; it < VPT; ++it, j += TPB) {
                if (j < ROW_VEC) {
                    const int base = j * 4;
                    float4 v = z;
                    int d;
                    d = c0 - base; if ((unsigned)d < 4u) ((float*)&v)[d] = 1.0f;
                    d = c1 - base; if ((unsigned)d < 4u) ((float*)&v)[d] = 1.0f;
                    d = c2 - base; if ((unsigned)d < 4u) ((float*)&v)[d] = 1.0f;
                    stcs4(&row_out[j], v);
                }
            }
        }
    }
}

extern "C" void kernel_launch(void* const* d_in, const int* in_sizes, int n_in,
                              void* d_out, int out_size) {
    // Inputs per metadata order: z (f32, unused), hID (i32), rID (i32), tID (i32)
    const int* hID = (const int*)d_in[1];
    const int* rID = (const int*)d_in[2];
    const int* tID = (const int*)d_in[3];
    float* out = (float*)d_out;

    fused_onehot_persistent<<<GRID_BLOCKS, TPB>>>(hID, rID, tID, out);
}